// round 3
// baseline (speedup 1.0000x reference)
#include <cuda_runtime.h>

#define N_NODES 50000
#define N_EDGES 800000
#define NFEAT   256
#define NCLASS  64

// ---------------- scratch (no allocations allowed) ----------------
__device__ float g_deg [N_NODES];
__device__ float g_dinv[N_NODES];
__device__ float g_norm[N_EDGES];
__device__ float g_buf0[N_NODES * NCLASS];
__device__ float g_buf1[N_NODES * NCLASS];

// ---------------- degree / normalization ----------------
__global__ void init_deg_kernel() {
    int i = blockIdx.x * blockDim.x + threadIdx.x;
    if (i < N_NODES) g_deg[i] = 1.0f;   // self-loop counted
}

__global__ void count_deg_kernel(const int* __restrict__ ei) {
    int e = blockIdx.x * blockDim.x + threadIdx.x;
    if (e < N_EDGES) {
        unsigned d = (unsigned)ei[N_EDGES + e];   // dst row
        if (d < N_NODES) atomicAdd(&g_deg[d], 1.0f);
    }
}

__global__ void dinv_kernel() {
    int i = blockIdx.x * blockDim.x + threadIdx.x;
    if (i < N_NODES) g_dinv[i] = rsqrtf(g_deg[i]);
}

__global__ void norm_kernel(const int* __restrict__ ei) {
    int e = blockIdx.x * blockDim.x + threadIdx.x;
    if (e < N_EDGES) {
        unsigned s = (unsigned)ei[e];
        unsigned d = (unsigned)ei[N_EDGES + e];
        float nv = 0.0f;
        if (s < N_NODES && d < N_NODES) nv = g_dinv[s] * g_dinv[d];
        g_norm[e] = nv;
    }
}

// ---------------- GEMM: Y0[50000,64] = x[50000,256] @ W[256,64] ----------------
// Block: 256 threads, 64 rows x 64 cols tile, k-tile 32. 4x4 register micro-tile.
__global__ void gemm_kernel(const float* __restrict__ x,
                            const float* __restrict__ W,
                            float* __restrict__ y) {
    __shared__ float xs[64][36];   // [row][k], padded for float4 stores
    __shared__ float ws[32][64];   // [k][col]

    int t  = threadIdx.x;
    int tx = t & 15;               // col group (tx*4 .. tx*4+3)
    int ty = t >> 4;               // row group (ty*4 .. ty*4+3)
    int row0 = blockIdx.x * 64;

    float acc[4][4];
#pragma unroll
    for (int r = 0; r < 4; r++)
#pragma unroll
        for (int c = 0; c < 4; c++) acc[r][c] = 0.0f;

    for (int k0 = 0; k0 < NFEAT; k0 += 32) {
        // load x tile: 64 rows x 32 k = 512 float4, 2 per thread
#pragma unroll
        for (int i = 0; i < 2; i++) {
            int idx = t + i * 256;
            int r   = idx >> 3;
            int kq  = idx & 7;
            int row = row0 + r;
            float4 v = make_float4(0.f, 0.f, 0.f, 0.f);
            if (row < N_NODES)
                v = *(const float4*)&x[row * NFEAT + k0 + kq * 4];
            *(float4*)&xs[r][kq * 4] = v;
        }
        // load W tile: 32 k x 64 cols = 512 float4, 2 per thread
#pragma unroll
        for (int i = 0; i < 2; i++) {
            int idx = t + i * 256;
            int kk  = idx >> 4;
            int cq  = idx & 15;
            float4 v = *(const float4*)&W[(k0 + kk) * NCLASS + cq * 4];
            *(float4*)&ws[kk][cq * 4] = v;
        }
        __syncthreads();

#pragma unroll
        for (int kk = 0; kk < 32; kk++) {
            float4 bb = *(const float4*)&ws[kk][tx * 4];
            float a0 = xs[ty * 4 + 0][kk];
            float a1 = xs[ty * 4 + 1][kk];
            float a2 = xs[ty * 4 + 2][kk];
            float a3 = xs[ty * 4 + 3][kk];
            acc[0][0] += a0 * bb.x; acc[0][1] += a0 * bb.y; acc[0][2] += a0 * bb.z; acc[0][3] += a0 * bb.w;
            acc[1][0] += a1 * bb.x; acc[1][1] += a1 * bb.y; acc[1][2] += a1 * bb.z; acc[1][3] += a1 * bb.w;
            acc[2][0] += a2 * bb.x; acc[2][1] += a2 * bb.y; acc[2][2] += a2 * bb.z; acc[2][3] += a2 * bb.w;
            acc[3][0] += a3 * bb.x; acc[3][1] += a3 * bb.y; acc[3][2] += a3 * bb.z; acc[3][3] += a3 * bb.w;
        }
        __syncthreads();
    }

#pragma unroll
    for (int r = 0; r < 4; r++) {
        int row = row0 + ty * 4 + r;
        if (row < N_NODES) {
            float4 o = make_float4(acc[r][0], acc[r][1], acc[r][2], acc[r][3]);
            *(float4*)&y[row * NCLASS + tx * 4] = o;
        }
    }
}

// ---------------- hop: y = selfnorm*x (+ optional bias), then scatter-add edges ----------------
__global__ void self_init_kernel(const float* __restrict__ xin,
                                 float* __restrict__ yout,
                                 const float* __restrict__ bias) {
    int t = blockIdx.x * blockDim.x + threadIdx.x;
    int i = t >> 4;
    int lane = t & 15;
    if (i >= N_NODES) return;
    float s = g_dinv[i]; s *= s;
    float4 v = ((const float4*)xin)[i * 16 + lane];
    v.x *= s; v.y *= s; v.z *= s; v.w *= s;
    if (bias) {
        float4 bb = ((const float4*)bias)[lane];
        v.x += bb.x; v.y += bb.y; v.z += bb.z; v.w += bb.w;
    }
    ((float4*)yout)[i * 16 + lane] = v;
}

__global__ void scatter_kernel(const int* __restrict__ ei,
                               const float* __restrict__ xin,
                               float* __restrict__ yout) {
    int t = blockIdx.x * blockDim.x + threadIdx.x;
    int e = t >> 4;                 // 16 lanes per edge (64 floats = 16 float4)
    int lane = t & 15;
    if (e >= N_EDGES) return;
    unsigned s = (unsigned)ei[e];
    unsigned d = (unsigned)ei[N_EDGES + e];
    if (s >= N_NODES || d >= N_NODES) return;
    float nv = g_norm[e];
    float4 v = ((const float4*)(xin + s * NCLASS))[lane];
    v.x *= nv; v.y *= nv; v.z *= nv; v.w *= nv;
    float4* dstp = ((float4*)(yout + d * NCLASS)) + lane;
    asm volatile("red.global.add.v4.f32 [%0], {%1, %2, %3, %4};"
                 :: "l"(dstp), "f"(v.x), "f"(v.y), "f"(v.z), "f"(v.w)
                 : "memory");
}

// ---------------- launch ----------------
extern "C" void kernel_launch(void* const* d_in, const int* in_sizes, int n_in,
                              void* d_out, int out_size) {
    const float* x  = (const float*)d_in[0];
    const int*   ei = (const int*)d_in[1];
    const float* W  = (const float*)d_in[2];
    const float* b  = (const float*)d_in[3];
    float* out = (float*)d_out;

    float *buf0, *buf1;
    cudaGetSymbolAddress((void**)&buf0, g_buf0);
    cudaGetSymbolAddress((void**)&buf1, g_buf1);

    const int T = 256;
    int gN  = (N_NODES + T - 1) / T;
    int gE  = (N_EDGES + T - 1) / T;
    int gN4 = (N_NODES * 16 + T - 1) / T;     // self_init: 16 threads/node
    int gE4 = (N_EDGES * 16 + T - 1) / T;     // scatter:   16 threads/edge
    int gG  = (N_NODES + 63) / 64;            // gemm blocks

    init_deg_kernel<<<gN, T>>>();
    count_deg_kernel<<<gE, T>>>(ei);
    dinv_kernel<<<gN, T>>>();
    norm_kernel<<<gE, T>>>(ei);

    // Y0 = x @ W  (propagation commutes with the linear layer)
    gemm_kernel<<<gG, T>>>(x, W, buf0);

    // hop 1: buf0 -> buf1
    self_init_kernel<<<gN4, T>>>(buf0, buf1, nullptr);
    scatter_kernel<<<gE4, T>>>(ei, buf0, buf1);
    // hop 2: buf1 -> buf0
    self_init_kernel<<<gN4, T>>>(buf1, buf0, nullptr);
    scatter_kernel<<<gE4, T>>>(ei, buf1, buf0);
    // hop 3: buf0 -> out (bias folded into the self/init pass)
    self_init_kernel<<<gN4, T>>>(buf0, out, b);
    scatter_kernel<<<gE4, T>>>(ei, buf0, out);
}

// round 4
// speedup vs baseline: 1.4926x; 1.4926x over previous
#include <cuda_runtime.h>

#define N_NODES 50000
#define N_EDGES 800000
#define NFEAT   256
#define NCLASS  64
#define SCAN_B  256
#define SCAN_G  ((N_NODES + SCAN_B - 1) / SCAN_B)   // 196

// ---------------- scratch (no allocations allowed) ----------------
__device__ int   g_cnt [N_NODES];       // in-degree (excl self)
__device__ int   g_ptr [N_NODES + 1];   // CSR row pointers (by dst)
__device__ int   g_cur [N_NODES];       // fill cursors
__device__ float g_dinv[N_NODES];
__device__ int   g_bsum[SCAN_B];
__device__ int   g_boff[SCAN_B];
__device__ int   g_csrc[N_EDGES];       // CSR: src node per slot
__device__ float g_cw  [N_EDGES];       // CSR: edge weight per slot
__device__ float g_buf0[N_NODES * NCLASS];
__device__ float g_buf1[N_NODES * NCLASS];

// ---------------- f32x2 packed helpers ----------------
__device__ __forceinline__ unsigned long long pack2(float x, float y) {
    unsigned long long d;
    asm("mov.b64 %0, {%1, %2};" : "=l"(d) : "f"(x), "f"(y));
    return d;
}
__device__ __forceinline__ unsigned long long fma2(unsigned long long a,
                                                   unsigned long long b,
                                                   unsigned long long c) {
    unsigned long long d;
    asm("fma.rn.f32x2 %0, %1, %2, %3;" : "=l"(d) : "l"(a), "l"(b), "l"(c));
    return d;
}
__device__ __forceinline__ void unpack2(unsigned long long d, float& x, float& y) {
    asm("mov.b64 {%0, %1}, %2;" : "=f"(x), "=f"(y) : "l"(d));
}

// ---------------- CSR build ----------------
__global__ void hist_kernel(const int* __restrict__ ei) {
    int e = blockIdx.x * blockDim.x + threadIdx.x;
    if (e < N_EDGES) {
        unsigned d = (unsigned)ei[N_EDGES + e];
        if (d < N_NODES) atomicAdd(&g_cnt[d], 1);
    }
}

// per-block inclusive scan -> exclusive offsets + block sums
__global__ void scan1_kernel() {
    __shared__ int s[SCAN_B];
    int t = threadIdx.x;
    int i = blockIdx.x * SCAN_B + t;
    int c = (i < N_NODES) ? g_cnt[i] : 0;
    s[t] = c;
    __syncthreads();
#pragma unroll
    for (int off = 1; off < SCAN_B; off <<= 1) {
        int v = (t >= off) ? s[t - off] : 0;
        __syncthreads();
        s[t] += v;
        __syncthreads();
    }
    if (i < N_NODES) g_ptr[i] = s[t] - c;       // exclusive within block
    if (t == SCAN_B - 1) g_bsum[blockIdx.x] = s[t];
}

__global__ void scan2_kernel() {
    __shared__ int s[SCAN_B];
    int t = threadIdx.x;
    int c = (t < SCAN_G) ? g_bsum[t] : 0;
    s[t] = c;
    __syncthreads();
#pragma unroll
    for (int off = 1; off < SCAN_B; off <<= 1) {
        int v = (t >= off) ? s[t - off] : 0;
        __syncthreads();
        s[t] += v;
        __syncthreads();
    }
    g_boff[t] = s[t] - c;                        // exclusive block offset
}

__global__ void scan3_kernel() {
    int i = blockIdx.x * blockDim.x + threadIdx.x;
    if (i < N_NODES) {
        int p = g_ptr[i] + g_boff[blockIdx.x * blockDim.x / SCAN_B + (threadIdx.x / SCAN_B)];
        // blockDim == SCAN_B so the above is just g_boff[blockIdx.x]
        p = g_ptr[i] + g_boff[blockIdx.x];
        g_ptr[i] = p;
        g_cur[i] = p;
        g_dinv[i] = rsqrtf((float)(g_cnt[i] + 1));   // +1 self loop
    }
    if (i == 0) g_ptr[N_NODES] = N_EDGES;
}

__global__ void fill_kernel(const int* __restrict__ ei) {
    int e = blockIdx.x * blockDim.x + threadIdx.x;
    if (e < N_EDGES) {
        unsigned s = (unsigned)ei[e];
        unsigned d = (unsigned)ei[N_EDGES + e];
        if (s < N_NODES && d < N_NODES) {
            int pos = atomicAdd(&g_cur[d], 1);
            g_csrc[pos] = (int)s;
            g_cw[pos]   = g_dinv[s] * g_dinv[d];
        }
    }
}

// ---------------- GEMM: Y0[50000,64] = x[50000,256] @ W[256,64] (f32x2 packed) ----------------
__global__ void gemm_kernel(const float* __restrict__ x,
                            const float* __restrict__ W,
                            float* __restrict__ y) {
    __shared__ float xs[64][36];                 // [row][k], padded for float4 stores
    __shared__ unsigned long long ws2[32][34];   // [k][col-pair], 16B-aligned rows

    int t  = threadIdx.x;
    int tx = t & 15;               // col group (cols tx*4 .. tx*4+3)
    int ty = t >> 4;               // row group (rows ty*4 .. ty*4+3)
    int row0 = blockIdx.x * 64;

    unsigned long long acc[4][2];
#pragma unroll
    for (int r = 0; r < 4; r++) { acc[r][0] = 0ULL; acc[r][1] = 0ULL; }

    for (int k0 = 0; k0 < NFEAT; k0 += 32) {
        // x tile: 64 rows x 32 k = 512 float4, 2 per thread
#pragma unroll
        for (int i = 0; i < 2; i++) {
            int idx = t + i * 256;
            int r   = idx >> 3;
            int kq  = idx & 7;
            int row = row0 + r;
            float4 v = make_float4(0.f, 0.f, 0.f, 0.f);
            if (row < N_NODES)
                v = *(const float4*)&x[row * NFEAT + k0 + kq * 4];
            *(float4*)&xs[r][kq * 4] = v;
        }
        // W tile: 32 k x 64 cols = 512 float4, stored as packed pairs
#pragma unroll
        for (int i = 0; i < 2; i++) {
            int idx = t + i * 256;
            int kk  = idx >> 4;
            int cq  = idx & 15;
            float4 v = *(const float4*)&W[(k0 + kk) * NCLASS + cq * 4];
            ws2[kk][cq * 2 + 0] = pack2(v.x, v.y);
            ws2[kk][cq * 2 + 1] = pack2(v.z, v.w);
        }
        __syncthreads();

#pragma unroll
        for (int kk = 0; kk < 32; kk++) {
            ulonglong2 b = *(const ulonglong2*)&ws2[kk][tx * 2];
#pragma unroll
            for (int r = 0; r < 4; r++) {
                float a = xs[ty * 4 + r][kk];
                unsigned long long ap = pack2(a, a);
                acc[r][0] = fma2(ap, b.x, acc[r][0]);
                acc[r][1] = fma2(ap, b.y, acc[r][1]);
            }
        }
        __syncthreads();
    }

#pragma unroll
    for (int r = 0; r < 4; r++) {
        int row = row0 + ty * 4 + r;
        if (row < N_NODES) {
            float4 o;
            unpack2(acc[r][0], o.x, o.y);
            unpack2(acc[r][1], o.z, o.w);
            *(float4*)&y[row * NCLASS + tx * 4] = o;
        }
    }
}

// ---------------- pull-based hop: y[i] = dinv_i^2 x[i] + sum_in w_e x[src] (+bias) ----------------
__global__ void hop_kernel(const float* __restrict__ xin,
                           float* __restrict__ yout,
                           const float* __restrict__ bias) {
    int t = blockIdx.x * blockDim.x + threadIdx.x;
    int node = t >> 4;
    int lane = t & 15;
    if (node >= N_NODES) return;

    int beg = g_ptr[node];
    int end = g_ptr[node + 1];
    float di = g_dinv[node];
    float w0 = di * di;

    float4 v = ((const float4*)(xin + node * NCLASS))[lane];
    float4 acc;
    acc.x = w0 * v.x; acc.y = w0 * v.y; acc.z = w0 * v.z; acc.w = w0 * v.w;
    if (bias) {
        float4 bb = ((const float4*)bias)[lane];
        acc.x += bb.x; acc.y += bb.y; acc.z += bb.z; acc.w += bb.w;
    }

    int j = beg;
    // unroll 2 for gather MLP
    for (; j + 1 < end; j += 2) {
        int   s0 = g_csrc[j];     int   s1 = g_csrc[j + 1];
        float w0e = g_cw[j];      float w1e = g_cw[j + 1];
        float4 u0 = ((const float4*)(xin + s0 * NCLASS))[lane];
        float4 u1 = ((const float4*)(xin + s1 * NCLASS))[lane];
        acc.x += w0e * u0.x; acc.y += w0e * u0.y; acc.z += w0e * u0.z; acc.w += w0e * u0.w;
        acc.x += w1e * u1.x; acc.y += w1e * u1.y; acc.z += w1e * u1.z; acc.w += w1e * u1.w;
    }
    if (j < end) {
        int   s0 = g_csrc[j];
        float we = g_cw[j];
        float4 u = ((const float4*)(xin + s0 * NCLASS))[lane];
        acc.x += we * u.x; acc.y += we * u.y; acc.z += we * u.z; acc.w += we * u.w;
    }

    ((float4*)(yout + node * NCLASS))[lane] = acc;
}

// ---------------- launch ----------------
extern "C" void kernel_launch(void* const* d_in, const int* in_sizes, int n_in,
                              void* d_out, int out_size) {
    const float* x  = (const float*)d_in[0];
    const int*   ei = (const int*)d_in[1];
    const float* W  = (const float*)d_in[2];
    const float* b  = (const float*)d_in[3];
    float* out = (float*)d_out;

    float *buf0, *buf1;
    cudaGetSymbolAddress((void**)&buf0, g_buf0);
    cudaGetSymbolAddress((void**)&buf1, g_buf1);
    int* cnt_ptr;
    cudaGetSymbolAddress((void**)&cnt_ptr, g_cnt);

    const int T = 256;
    int gE  = (N_EDGES + T - 1) / T;
    int gH  = (N_NODES * 16 + T - 1) / T;     // hop: 16 threads/node
    int gG  = (N_NODES + 63) / 64;            // gemm blocks

    // CSR build
    cudaMemsetAsync(cnt_ptr, 0, N_NODES * sizeof(int));
    hist_kernel<<<gE, T>>>(ei);
    scan1_kernel<<<SCAN_G, SCAN_B>>>();
    scan2_kernel<<<1, SCAN_B>>>();
    scan3_kernel<<<SCAN_G, SCAN_B>>>();
    fill_kernel<<<gE, T>>>(ei);

    // Y0 = x @ W  (propagation commutes with the linear layer)
    gemm_kernel<<<gG, T>>>(x, W, buf0);

    // 3 pull-based hops
    hop_kernel<<<gH, T>>>(buf0, buf1, nullptr);
    hop_kernel<<<gH, T>>>(buf1, buf0, nullptr);
    hop_kernel<<<gH, T>>>(buf0, out, b);
}

// round 5
// speedup vs baseline: 1.6879x; 1.1309x over previous
#include <cuda_runtime.h>

#define N_NODES 50000
#define N_EDGES 800000
#define NFEAT   256
#define NCLASS  64
#define SCAN_B  256
#define SCAN_G  ((N_NODES + SCAN_B - 1) / SCAN_B)   // 196

typedef unsigned long long ull;

// ---------------- scratch (no allocations allowed) ----------------
__device__ int   g_cnt [N_NODES];       // in-degree (excl self)
__device__ int   g_ptr [N_NODES + 1];   // CSR row pointers (by dst)
__device__ int   g_cur [N_NODES];       // fill cursors
__device__ float g_dinv[N_NODES];
__device__ int   g_bsum[SCAN_B];
__device__ int   g_boff[SCAN_B];
__device__ ull   g_rec [N_EDGES];       // CSR slot: {w (hi 32), src (lo 32)}
__device__ float g_buf0[N_NODES * NCLASS];
__device__ float g_buf1[N_NODES * NCLASS];

// ---------------- streams/events for fork-join capture ----------------
static cudaStream_t g_s1;
static cudaEvent_t  g_evFork, g_evJoin;
static struct SideInit {
    SideInit() {
        cudaStreamCreateWithFlags(&g_s1, cudaStreamNonBlocking);
        cudaEventCreateWithFlags(&g_evFork, cudaEventDisableTiming);
        cudaEventCreateWithFlags(&g_evJoin, cudaEventDisableTiming);
    }
} g_sideInit;

// ---------------- f32x2 packed helpers ----------------
__device__ __forceinline__ ull pack2(float x, float y) {
    ull d;
    asm("mov.b64 %0, {%1, %2};" : "=l"(d) : "f"(x), "f"(y));
    return d;
}
__device__ __forceinline__ ull fma2(ull a, ull b, ull c) {
    ull d;
    asm("fma.rn.f32x2 %0, %1, %2, %3;" : "=l"(d) : "l"(a), "l"(b), "l"(c));
    return d;
}
__device__ __forceinline__ void unpack2(ull d, float& x, float& y) {
    asm("mov.b64 {%0, %1}, %2;" : "=f"(x), "=f"(y) : "l"(d));
}

// ---------------- CSR build ----------------
__global__ void hist_kernel(const int* __restrict__ ei) {
    int e = blockIdx.x * blockDim.x + threadIdx.x;
    if (e < N_EDGES) {
        unsigned d = (unsigned)ei[N_EDGES + e];
        if (d < N_NODES) atomicAdd(&g_cnt[d], 1);
    }
}

// per-block inclusive scan -> exclusive offsets within block + block sums
__global__ void scan1_kernel() {
    __shared__ int s[SCAN_B];
    int t = threadIdx.x;
    int i = blockIdx.x * SCAN_B + t;
    int c = (i < N_NODES) ? g_cnt[i] : 0;
    s[t] = c;
    __syncthreads();
#pragma unroll
    for (int off = 1; off < SCAN_B; off <<= 1) {
        int v = (t >= off) ? s[t - off] : 0;
        __syncthreads();
        s[t] += v;
        __syncthreads();
    }
    if (i < N_NODES) g_ptr[i] = s[t] - c;       // exclusive within block
    if (t == SCAN_B - 1) g_bsum[blockIdx.x] = s[t];
}

__global__ void scan2_kernel() {
    __shared__ int s[SCAN_B];
    int t = threadIdx.x;
    int c = (t < SCAN_G) ? g_bsum[t] : 0;
    s[t] = c;
    __syncthreads();
#pragma unroll
    for (int off = 1; off < SCAN_B; off <<= 1) {
        int v = (t >= off) ? s[t - off] : 0;
        __syncthreads();
        s[t] += v;
        __syncthreads();
    }
    g_boff[t] = s[t] - c;                        // exclusive block offset
}

__global__ void scan3_kernel() {
    int i = blockIdx.x * blockDim.x + threadIdx.x;
    if (i < N_NODES) {
        int p = g_ptr[i] + g_boff[blockIdx.x];
        g_ptr[i] = p;
        g_cur[i] = p;
        g_dinv[i] = rsqrtf((float)(g_cnt[i] + 1));   // +1 self loop
    }
    if (i == 0) g_ptr[N_NODES] = N_EDGES;
}

__global__ void fill_kernel(const int* __restrict__ ei) {
    int e = blockIdx.x * blockDim.x + threadIdx.x;
    if (e < N_EDGES) {
        unsigned s = (unsigned)ei[e];
        unsigned d = (unsigned)ei[N_EDGES + e];
        if (s < N_NODES && d < N_NODES) {
            int pos = atomicAdd(&g_cur[d], 1);
            float w = g_dinv[s] * g_dinv[d];
            g_rec[pos] = ((ull)__float_as_uint(w) << 32) | (ull)s;
        }
    }
}

// ---------------- GEMM: Y0[50000,64] = x[50000,256] @ W[256,64] (f32x2 packed) ----------------
__global__ void gemm_kernel(const float* __restrict__ x,
                            const float* __restrict__ W,
                            float* __restrict__ y) {
    __shared__ float xs[64][36];   // [row][k], padded for float4 stores
    __shared__ ull   ws2[32][34];  // [k][col-pair], 16B-aligned rows

    int t  = threadIdx.x;
    int tx = t & 15;               // col group (cols tx*4 .. tx*4+3)
    int ty = t >> 4;               // row group (rows ty*4 .. ty*4+3)
    int row0 = blockIdx.x * 64;

    ull acc[4][2];
#pragma unroll
    for (int r = 0; r < 4; r++) { acc[r][0] = 0ULL; acc[r][1] = 0ULL; }

    for (int k0 = 0; k0 < NFEAT; k0 += 32) {
#pragma unroll
        for (int i = 0; i < 2; i++) {
            int idx = t + i * 256;
            int r   = idx >> 3;
            int kq  = idx & 7;
            int row = row0 + r;
            float4 v = make_float4(0.f, 0.f, 0.f, 0.f);
            if (row < N_NODES)
                v = *(const float4*)&x[row * NFEAT + k0 + kq * 4];
            *(float4*)&xs[r][kq * 4] = v;
        }
#pragma unroll
        for (int i = 0; i < 2; i++) {
            int idx = t + i * 256;
            int kk  = idx >> 4;
            int cq  = idx & 15;
            float4 v = *(const float4*)&W[(k0 + kk) * NCLASS + cq * 4];
            ws2[kk][cq * 2 + 0] = pack2(v.x, v.y);
            ws2[kk][cq * 2 + 1] = pack2(v.z, v.w);
        }
        __syncthreads();

#pragma unroll
        for (int kk = 0; kk < 32; kk++) {
            ulonglong2 b = *(const ulonglong2*)&ws2[kk][tx * 2];
#pragma unroll
            for (int r = 0; r < 4; r++) {
                float a = xs[ty * 4 + r][kk];
                ull ap = pack2(a, a);
                acc[r][0] = fma2(ap, b.x, acc[r][0]);
                acc[r][1] = fma2(ap, b.y, acc[r][1]);
            }
        }
        __syncthreads();
    }

#pragma unroll
    for (int r = 0; r < 4; r++) {
        int row = row0 + ty * 4 + r;
        if (row < N_NODES) {
            float4 o;
            unpack2(acc[r][0], o.x, o.y);
            unpack2(acc[r][1], o.z, o.w);
            *(float4*)&y[row * NCLASS + tx * 4] = o;
        }
    }
}

// ---------------- pull-based hop (warp per node, float2 per lane) ----------------
// y[i] = dinv_i^2 * x[i] + sum_{e: dst=i} w_e * x[src_e]  (+ bias)
__global__ void hop_kernel(const float* __restrict__ xin,
                           float* __restrict__ yout,
                           const float* __restrict__ bias) {
    int gtid = blockIdx.x * blockDim.x + threadIdx.x;
    int node = gtid >> 5;
    int lane = threadIdx.x & 31;
    if (node >= N_NODES) return;

    int beg = g_ptr[node];
    int end = g_ptr[node + 1];
    float di = g_dinv[node];
    float w0 = di * di;

    ull v = *(const ull*)(xin + node * NCLASS + lane * 2);
    ull base = bias ? *(const ull*)(bias + lane * 2) : 0ULL;
    ull acc = fma2(pack2(w0, w0), v, base);

    int j = beg;
    for (; j + 1 < end; j += 2) {
        ull r0 = g_rec[j];
        ull r1 = g_rec[j + 1];
        int   s0 = (int)(unsigned)r0;
        int   s1 = (int)(unsigned)r1;
        float wa = __uint_as_float((unsigned)(r0 >> 32));
        float wb = __uint_as_float((unsigned)(r1 >> 32));
        ull u0 = *(const ull*)(xin + s0 * NCLASS + lane * 2);
        ull u1 = *(const ull*)(xin + s1 * NCLASS + lane * 2);
        acc = fma2(pack2(wa, wa), u0, acc);
        acc = fma2(pack2(wb, wb), u1, acc);
    }
    if (j < end) {
        ull r0 = g_rec[j];
        int   s0 = (int)(unsigned)r0;
        float wa = __uint_as_float((unsigned)(r0 >> 32));
        ull u0 = *(const ull*)(xin + s0 * NCLASS + lane * 2);
        acc = fma2(pack2(wa, wa), u0, acc);
    }

    *(ull*)(yout + node * NCLASS + lane * 2) = acc;
}

// ---------------- launch ----------------
extern "C" void kernel_launch(void* const* d_in, const int* in_sizes, int n_in,
                              void* d_out, int out_size) {
    const float* x  = (const float*)d_in[0];
    const int*   ei = (const int*)d_in[1];
    const float* W  = (const float*)d_in[2];
    const float* b  = (const float*)d_in[3];
    float* out = (float*)d_out;

    float *buf0, *buf1;
    cudaGetSymbolAddress((void**)&buf0, g_buf0);
    cudaGetSymbolAddress((void**)&buf1, g_buf1);
    int* cnt_ptr;
    cudaGetSymbolAddress((void**)&cnt_ptr, g_cnt);

    const int T = 256;
    int gE = (N_EDGES + T - 1) / T;
    int gH = (N_NODES * 32 + T - 1) / T;      // hop: warp per node
    int gG = (N_NODES + 63) / 64;             // gemm blocks

    // Fork: GEMM (depends only on x, W) runs on side stream, concurrent
    // with the CSR build (depends only on edge_index).
    cudaEventRecord(g_evFork, 0);
    cudaStreamWaitEvent(g_s1, g_evFork, 0);
    gemm_kernel<<<gG, T, 0, g_s1>>>(x, W, buf0);
    cudaEventRecord(g_evJoin, g_s1);

    // CSR build on main stream
    cudaMemsetAsync(cnt_ptr, 0, N_NODES * sizeof(int), 0);
    hist_kernel<<<gE, T>>>(ei);
    scan1_kernel<<<SCAN_G, SCAN_B>>>();
    scan2_kernel<<<1, SCAN_B>>>();
    scan3_kernel<<<SCAN_G, SCAN_B>>>();
    fill_kernel<<<gE, T>>>(ei);

    // Join: hops need both buf0 (GEMM) and the CSR
    cudaStreamWaitEvent(0, g_evJoin, 0);

    hop_kernel<<<gH, T>>>(buf0, buf1, nullptr);
    hop_kernel<<<gH, T>>>(buf1, buf0, nullptr);
    hop_kernel<<<gH, T>>>(buf0, out, b);
}